// round 9
// baseline (speedup 1.0000x reference)
#include <cuda_runtime.h>
#include <cstdint>

#define H      128
#define INW    86
#define OUTW   66
#define GATES  512
#define TSEQ   50
#define NSTEP  65
#define RSTEPS 15
#define BT     64
#define NTHR   256

#define KT0    27    // layer0 k-tiles: 11 (u, K=88 padded) + 16 (h1)
#define KT1    32    // layer1: 16 (h1) + 16 (h2)
#define UP     92    // u smem pitch
#define HP     132   // h smem pitch
#define WP     68    // WdT smem pitch

#define OFF_U   0
#define OFF_H1  (BT * UP)
#define HBUF    (BT * HP)
#define OFF_H2  (OFF_H1 + 2 * HBUF)
#define OFF_WD  (OFF_H2 + 2 * HBUF)
#define OFF_B0  (OFF_WD + H * WP)
#define OFF_B1  (OFF_B0 + GATES)
#define SMEM_FLOATS (OFF_B1 + GATES)
#define SMEM_BYTES  (SMEM_FLOATS * 4)

// packed weight fragments: idx = kt*1024 + nh*512 + g*128 + utp*32 + lane
// float4 = { B(k=t4,ut=2utp), B(t4+4,2utp), B(t4,2utp+1), B(t4+4,2utp+1) }, n=gid
// B(k,n) = W[g*128 + nh*64 + ut*8 + n][kt*8 + k];  hi/lo = split-tf32 pair.
__device__ float4 g_B0h[KT0 * 1024], g_B0l[KT0 * 1024];
__device__ float4 g_B1h[KT1 * 1024], g_B1l[KT1 * 1024];
__device__ float  g_Wd[H * WP];
__device__ float  g_b0[GATES];
__device__ float  g_b1[GATES];

__device__ __forceinline__ uint32_t cvtf(float x){
  uint32_t r; asm("cvt.rna.tf32.f32 %0, %1;" : "=r"(r) : "f"(x)); return r;
}
__device__ __forceinline__ float tf32r(float x){ return __uint_as_float(cvtf(x)); }
__device__ __forceinline__ void mma8(float* d, uint32_t a0, uint32_t a1, uint32_t a2, uint32_t a3,
                                     float bx, float by){
  asm volatile("mma.sync.aligned.m16n8k8.row.col.f32.tf32.tf32.f32 "
               "{%0,%1,%2,%3},{%4,%5,%6,%7},{%8,%9},{%0,%1,%2,%3};"
               : "+f"(d[0]), "+f"(d[1]), "+f"(d[2]), "+f"(d[3])
               : "r"(a0), "r"(a1), "r"(a2), "r"(a3),
                 "r"(__float_as_uint(bx)), "r"(__float_as_uint(by)));
}
__device__ __forceinline__ float sigf(float x){ return __fdividef(1.0f, 1.0f + __expf(-x)); }
__device__ __forceinline__ float tanhfast(float x){ return __fdividef(2.0f, 1.0f + __expf(-2.0f * x)) - 1.0f; }

// GEMM over NKT k-tiles, 3xTF32: acc += Ah*Bh + Ah*Bl + Al*Bh
template<int NKT>
__device__ __forceinline__ void gemm_part(float acc[4][8][4], const float* __restrict__ Abase,
                                          int pitch, const float4* __restrict__ Bh,
                                          const float4* __restrict__ Bl, int gid, int t4)
{
  #pragma unroll 2
  for (int kt = 0; kt < NKT; ++kt) {
    const float* ar = Abase + kt * 8 + t4;
    float a0f = ar[gid * pitch],     a1f = ar[(gid + 8) * pitch];
    float a2f = ar[gid * pitch + 4], a3f = ar[(gid + 8) * pitch + 4];
    uint32_t h0 = cvtf(a0f), h1 = cvtf(a1f), h2 = cvtf(a2f), h3 = cvtf(a3f);
    uint32_t l0 = cvtf(a0f - __uint_as_float(h0));
    uint32_t l1 = cvtf(a1f - __uint_as_float(h1));
    uint32_t l2 = cvtf(a2f - __uint_as_float(h2));
    uint32_t l3 = cvtf(a3f - __uint_as_float(h3));
    const float4* bh = Bh + kt * 1024;
    const float4* bl = Bl + kt * 1024;
    #pragma unroll
    for (int g = 0; g < 4; ++g)
      #pragma unroll
      for (int utp = 0; utp < 4; ++utp) {
        float4 bhv = __ldg(bh + (g * 4 + utp) * 32);
        float4 blv = __ldg(bl + (g * 4 + utp) * 32);
        float* d0 = acc[g][2 * utp];
        float* d1 = acc[g][2 * utp + 1];
        mma8(d0, h0, h1, h2, h3, bhv.x, bhv.y);
        mma8(d0, h0, h1, h2, h3, blv.x, blv.y);
        mma8(d0, l0, l1, l2, l3, bhv.x, bhv.y);
        mma8(d1, h0, h1, h2, h3, bhv.z, bhv.w);
        mma8(d1, h0, h1, h2, h3, blv.z, blv.w);
        mma8(d1, l0, l1, l2, l3, bhv.z, bhv.w);
      }
  }
}

__device__ __forceinline__ void bias_init(float acc[4][8][4], const float* __restrict__ bS,
                                          int ncol0, int t4)
{
  #pragma unroll
  for (int g = 0; g < 4; ++g)
    #pragma unroll
    for (int ut = 0; ut < 8; ++ut) {
      float2 bb = *reinterpret_cast<const float2*>(&bS[g * 128 + ncol0 + ut * 8 + 2 * t4]);
      acc[g][ut][0] = bb.x; acc[g][ut][1] = bb.y;
      acc[g][ut][2] = bb.x; acc[g][ut][3] = bb.y;
    }
}

// slots: 0,1 -> row rbase+gid cols c,c+1 ; 2,3 -> row rbase+gid+8
__device__ __forceinline__ void cell_store(float acc[4][8][4], float cst[8][4],
                                           float* __restrict__ hb,
                                           int rbase, int gid, int t4, int ncol0)
{
  #pragma unroll
  for (int ut = 0; ut < 8; ++ut) {
    float hv[4];
    #pragma unroll
    for (int sl = 0; sl < 4; ++sl) {
      float cc = sigf(acc[1][ut][sl]) * cst[ut][sl]
               + sigf(acc[0][ut][sl]) * tanhfast(acc[2][ut][sl]);
      cst[ut][sl] = cc;
      hv[sl] = sigf(acc[3][ut][sl]) * tanhfast(cc);
    }
    int c = ncol0 + ut * 8 + 2 * t4;
    *reinterpret_cast<float2*>(&hb[(rbase + gid) * HP + c])     = make_float2(hv[0], hv[1]);
    *reinterpret_cast<float2*>(&hb[(rbase + gid + 8) * HP + c]) = make_float2(hv[2], hv[3]);
  }
}

__global__ void prep_kernel(const float* __restrict__ Wih0, const float* __restrict__ Whh0,
                            const float* __restrict__ bih0, const float* __restrict__ bhh0,
                            const float* __restrict__ Wih1, const float* __restrict__ Whh1,
                            const float* __restrict__ bih1, const float* __restrict__ bhh1,
                            const float* __restrict__ Wd)
{
  int j = blockIdx.x * blockDim.x + threadIdx.x;
  const int NB = (KT0 + KT1) * 1024;
  if (j < NB) {
    int lay = (j >= KT0 * 1024);
    int jj  = lay ? j - KT0 * 1024 : j;
    int kt  = jj >> 10;
    int r   = jj & 1023;
    int nh  = r >> 9;  r &= 511;
    int g   = r >> 7;  r &= 127;
    int utp = r >> 5;
    int lane = r & 31;
    int gid = lane >> 2, t4 = lane & 3;
    float vh[4], vl[4];
    #pragma unroll
    for (int jx = 0; jx < 4; ++jx) {
      int ut = utp * 2 + (jx >> 1);
      int k  = t4 + 4 * (jx & 1);
      int grow = g * 128 + nh * 64 + ut * 8 + gid;
      float val;
      if (!lay) {
        if (kt < 11) { int col = kt * 8 + k; val = (col < INW) ? Wih0[grow * INW + col] : 0.0f; }
        else         { val = Whh0[grow * H + (kt - 11) * 8 + k]; }
      } else {
        if (kt < 16) val = Wih1[grow * H + kt * 8 + k];
        else         val = Whh1[grow * H + (kt - 16) * 8 + k];
      }
      vh[jx] = tf32r(val);
      vl[jx] = tf32r(val - vh[jx]);
    }
    if (!lay) { g_B0h[jj] = make_float4(vh[0], vh[1], vh[2], vh[3]);
                g_B0l[jj] = make_float4(vl[0], vl[1], vl[2], vl[3]); }
    else      { g_B1h[jj] = make_float4(vh[0], vh[1], vh[2], vh[3]);
                g_B1l[jj] = make_float4(vl[0], vl[1], vl[2], vl[3]); }
    return;
  }
  j -= NB;
  if (j < H * WP) {
    int kk = j / WP, o = j % WP;
    g_Wd[j] = (o < OUTW) ? Wd[o * H + kk] : 0.0f;
    return;
  }
  j -= H * WP;
  if (j < GATES) { g_b0[j] = bih0[j] + bhh0[j]; return; }
  j -= GATES;
  if (j < GATES) { g_b1[j] = bih1[j] + bhh1[j]; return; }
}

__global__ void __launch_bounds__(NTHR, 1)
lstm_main(const float* __restrict__ x, const float* __restrict__ bd, float* __restrict__ out)
{
  extern __shared__ float sm[];
  float* uS  = sm + OFF_U;     // [64][UP] cols 86..91 zero
  float* h1S = sm + OFF_H1;    // [2][64][HP]
  float* h2S = sm + OFF_H2;
  float* wdS = sm + OFF_WD;    // [128][WP]
  float* b0S = sm + OFF_B0;
  float* b1S = sm + OFF_B1;

  const int tid  = threadIdx.x;
  const int lane = tid & 31, w = tid >> 5;
  const int mw = w & 3, nh = w >> 2;
  const int gid = lane >> 2, t4 = lane & 3;
  const int rbase = mw * 16;
  const int row0  = blockIdx.x * BT;
  const int ncol0 = nh * 64;

  for (int i = tid; i < 2 * HBUF; i += NTHR) { h1S[i] = 0.0f; h2S[i] = 0.0f; }
  for (int i = tid; i < BT * UP; i += NTHR) uS[i] = 0.0f;
  for (int i = tid; i < H * WP; i += NTHR) wdS[i] = g_Wd[i];
  for (int i = tid; i < GATES; i += NTHR) { b0S[i] = g_b0[i]; b1S[i] = g_b1[i]; }
  __syncthreads();
  for (int i = tid; i < BT * INW; i += NTHR) {
    int r = i / INW, c = i % INW;
    uS[r * UP + c] = x[(size_t)(row0 + r) * (TSEQ * INW) + c];
  }

  float c1[8][4], c2[8][4];
  #pragma unroll
  for (int ut = 0; ut < 8; ++ut)
    #pragma unroll
    for (int sl = 0; sl < 4; ++sl) { c1[ut][sl] = 0.0f; c2[ut][sl] = 0.0f; }

  const float4* b0h = g_B0h + nh * 512 + lane;
  const float4* b0l = g_B0l + nh * 512 + lane;
  const float4* b1h = g_B1h + nh * 512 + lane;
  const float4* b1l = g_B1l + nh * 512 + lane;
  __syncthreads();

  for (int s = 0; s < NSTEP; ++s) {
    const int cur = s & 1, nxt = cur ^ 1;
    float acc[4][8][4];

    // layer 0
    bias_init(acc, b0S, ncol0, t4);
    gemm_part<11>(acc, uS + rbase * UP, UP, b0h, b0l, gid, t4);
    gemm_part<16>(acc, h1S + cur * HBUF + rbase * HP, HP,
                  b0h + 11 * 1024, b0l + 11 * 1024, gid, t4);
    cell_store(acc, c1, h1S + nxt * HBUF, rbase, gid, t4, ncol0);
    __syncthreads();   // h1[nxt] visible; uS reads done

    if (s + 1 <= TSEQ) {
      int t = (s + 1 < TSEQ) ? (s + 1) : (TSEQ - 1);
      for (int i = tid; i < BT * INW; i += NTHR) {
        int r = i / INW, c = i % INW;
        uS[r * UP + c] = x[(size_t)(row0 + r) * (TSEQ * INW) + t * INW + c];
      }
    }

    // layer 1
    bias_init(acc, b1S, ncol0, t4);
    gemm_part<16>(acc, h1S + nxt * HBUF + rbase * HP, HP, b1h, b1l, gid, t4);
    gemm_part<16>(acc, h2S + cur * HBUF + rbase * HP, HP,
                  b1h + 16 * 1024, b1l + 16 * 1024, gid, t4);
    cell_store(acc, c2, h2S + nxt * HBUF, rbase, gid, t4, ncol0);
    __syncthreads();   // h2[nxt] + staged u visible

    // dense head (steps 50..64)
    if (s >= TSEQ) {
      const int so = s - TSEQ;
      const int r = 8 * w + gid;
      const float* h2r = h2S + nxt * HBUF + r * HP;
      float pose[17];
      #pragma unroll
      for (int jj = 0; jj < 17; ++jj) {
        int o = t4 + 4 * jj;
        pose[jj] = (o < OUTW) ? __ldg(bd + o) : 0.0f;
      }
      #pragma unroll 4
      for (int kk = 0; kk < H; ++kk) {
        float hv = h2r[kk];
        const float* wr = wdS + kk * WP + t4;
        #pragma unroll
        for (int jj = 0; jj < 17; ++jj) pose[jj] += hv * wr[4 * jj];
      }
      float* uR = uS + r * UP;
      #pragma unroll
      for (int jj = 0; jj < 17; ++jj) {
        int o = t4 + 4 * jj;
        if (o < OUTW) {
          out[(size_t)(row0 + r) * (RSTEPS * OUTW) + so * OUTW + o] = pose[jj];
          uR[o] = pose[jj];   // pose -> next u[0..65]; cond cols 66..85 persist
        }
      }
      __syncthreads(); // pose visible for next layer0
    }
  }
}

extern "C" void kernel_launch(void* const* d_in, const int* in_sizes, int n_in,
                              void* d_out, int out_size)
{
  const float* x    = (const float*)d_in[0];
  const float* Wih0 = (const float*)d_in[1];
  const float* Whh0 = (const float*)d_in[2];
  const float* bih0 = (const float*)d_in[3];
  const float* bhh0 = (const float*)d_in[4];
  const float* Wih1 = (const float*)d_in[5];
  const float* Whh1 = (const float*)d_in[6];
  const float* bih1 = (const float*)d_in[7];
  const float* bhh1 = (const float*)d_in[8];
  const float* Wd   = (const float*)d_in[9];
  const float* bd   = (const float*)d_in[10];
  float* out = (float*)d_out;

  const int B = in_sizes[0] / (TSEQ * INW);   // 8192

  cudaFuncSetAttribute(lstm_main, cudaFuncAttributeMaxDynamicSharedMemorySize, SMEM_BYTES);

  const int prep_n = (KT0 + KT1) * 1024 + H * WP + 2 * GATES;
  prep_kernel<<<(prep_n + 255) / 256, 256>>>(Wih0, Whh0, bih0, bhh0,
                                             Wih1, Whh1, bih1, bhh1, Wd);
  lstm_main<<<B / BT, NTHR, SMEM_BYTES>>>(x, bd, out);
}

// round 10
// speedup vs baseline: 2.4164x; 2.4164x over previous
#include <cuda_runtime.h>
#include <cstdint>

#define H      128
#define INW    86
#define OUTW   66
#define GATES  512
#define TSEQ   50
#define NSTEP  65
#define RSTEPS 15
#define BT     64
#define NTHR   512

#define KT0    27    // layer0 k-tiles: 11 (u, K=88 padded) + 16 (h1)
#define KT1    32    // layer1: 16 (h1) + 16 (h2)
#define UP     92    // u smem pitch
#define HP     132   // h smem pitch
#define WP     72    // WdT smem pitch (cols 66..71 zero)

#define OFF_U   0
#define OFF_H1  (BT * UP)
#define HBUF    (BT * HP)
#define OFF_H2  (OFF_H1 + 2 * HBUF)
#define OFF_WD  (OFF_H2 + 2 * HBUF)
#define OFF_B0  (OFF_WD + H * WP)
#define OFF_B1  (OFF_B0 + GATES)
#define SMEM_FLOATS (OFF_B1 + GATES)
#define SMEM_BYTES  (SMEM_FLOATS * 4)   // ~200 KB

// packed tf32 weight fragments (single, hi only):
// idx = kt*1024 + nh*256 + g*64 + utp*32 + lane
// float4 = { B(k=t4,ut=2utp), B(t4+4,2utp), B(t4,2utp+1), B(t4+4,2utp+1) }, n=gid
// B(k,n) = W[g*128 + nh*32 + ut*8 + n][kbase + k]
__device__ float4 g_F0[KT0 * 1024];
__device__ float4 g_F1[KT1 * 1024];
__device__ float  g_Wd[H * WP];
__device__ float  g_b0[GATES];
__device__ float  g_b1[GATES];

__device__ __forceinline__ uint32_t cvtf(float x){
  uint32_t r; asm("cvt.rna.tf32.f32 %0, %1;" : "=r"(r) : "f"(x)); return r;
}
__device__ __forceinline__ float tf32r(float x){ return __uint_as_float(cvtf(x)); }
__device__ __forceinline__ void mma8(float* d, uint32_t a0, uint32_t a1, uint32_t a2, uint32_t a3,
                                     float bx, float by){
  asm volatile("mma.sync.aligned.m16n8k8.row.col.f32.tf32.tf32.f32 "
               "{%0,%1,%2,%3},{%4,%5,%6,%7},{%8,%9},{%0,%1,%2,%3};"
               : "+f"(d[0]), "+f"(d[1]), "+f"(d[2]), "+f"(d[3])
               : "r"(a0), "r"(a1), "r"(a2), "r"(a3),
                 "r"(__float_as_uint(bx)), "r"(__float_as_uint(by)));
}
__device__ __forceinline__ float sigf(float x){ return __fdividef(1.0f, 1.0f + __expf(-x)); }
__device__ __forceinline__ float tanhfast(float x){ return __fdividef(2.0f, 1.0f + __expf(-2.0f * x)) - 1.0f; }

// 2-term compensated GEMM: acc += Ah*B + Al*B  (A split at runtime, B tf32 from prep)
template<int NKT>
__device__ __forceinline__ void gemm_part(float acc[4][4][4], const float* __restrict__ Abase,
                                          int pitch, const float4* __restrict__ bp0,
                                          int gid, int t4)
{
  #pragma unroll 2
  for (int kt = 0; kt < NKT; ++kt) {
    const float* ar = Abase + kt * 8 + t4;
    float a0f = ar[gid * pitch],     a1f = ar[(gid + 8) * pitch];
    float a2f = ar[gid * pitch + 4], a3f = ar[(gid + 8) * pitch + 4];
    uint32_t h0 = cvtf(a0f), h1 = cvtf(a1f), h2 = cvtf(a2f), h3 = cvtf(a3f);
    uint32_t l0 = cvtf(a0f - __uint_as_float(h0));
    uint32_t l1 = cvtf(a1f - __uint_as_float(h1));
    uint32_t l2 = cvtf(a2f - __uint_as_float(h2));
    uint32_t l3 = cvtf(a3f - __uint_as_float(h3));
    const float4* bb = bp0 + kt * 1024;
    #pragma unroll
    for (int g = 0; g < 4; ++g)
      #pragma unroll
      for (int utp = 0; utp < 2; ++utp) {
        float4 bv = __ldg(bb + (g * 2 + utp) * 32);
        float* d0 = acc[g][2 * utp];
        float* d1 = acc[g][2 * utp + 1];
        mma8(d0, h0, h1, h2, h3, bv.x, bv.y);
        mma8(d0, l0, l1, l2, l3, bv.x, bv.y);
        mma8(d1, h0, h1, h2, h3, bv.z, bv.w);
        mma8(d1, l0, l1, l2, l3, bv.z, bv.w);
      }
  }
}

__device__ __forceinline__ void bias_init(float acc[4][4][4], const float* __restrict__ bS,
                                          int ncol0, int t4)
{
  #pragma unroll
  for (int g = 0; g < 4; ++g)
    #pragma unroll
    for (int ut = 0; ut < 4; ++ut) {
      float2 bb = *reinterpret_cast<const float2*>(&bS[g * 128 + ncol0 + ut * 8 + 2 * t4]);
      acc[g][ut][0] = bb.x; acc[g][ut][1] = bb.y;
      acc[g][ut][2] = bb.x; acc[g][ut][3] = bb.y;
    }
}

// slots: 0,1 -> row rbase+gid cols c,c+1 ; 2,3 -> row rbase+gid+8
__device__ __forceinline__ void cell_store(float acc[4][4][4], float cst[4][4],
                                           float* __restrict__ hb,
                                           int rbase, int gid, int t4, int ncol0)
{
  #pragma unroll
  for (int ut = 0; ut < 4; ++ut) {
    float hv[4];
    #pragma unroll
    for (int sl = 0; sl < 4; ++sl) {
      float cc = sigf(acc[1][ut][sl]) * cst[ut][sl]
               + sigf(acc[0][ut][sl]) * tanhfast(acc[2][ut][sl]);
      cst[ut][sl] = cc;
      hv[sl] = sigf(acc[3][ut][sl]) * tanhfast(cc);
    }
    int c = ncol0 + ut * 8 + 2 * t4;
    *reinterpret_cast<float2*>(&hb[(rbase + gid) * HP + c])     = make_float2(hv[0], hv[1]);
    *reinterpret_cast<float2*>(&hb[(rbase + gid + 8) * HP + c]) = make_float2(hv[2], hv[3]);
  }
}

__global__ void prep_kernel(const float* __restrict__ Wih0, const float* __restrict__ Whh0,
                            const float* __restrict__ bih0, const float* __restrict__ bhh0,
                            const float* __restrict__ Wih1, const float* __restrict__ Whh1,
                            const float* __restrict__ bih1, const float* __restrict__ bhh1,
                            const float* __restrict__ Wd)
{
  int j = blockIdx.x * blockDim.x + threadIdx.x;
  const int NB = (KT0 + KT1) * 1024;
  if (j < NB) {
    int lay = (j >= KT0 * 1024);
    int jj  = lay ? j - KT0 * 1024 : j;
    int kt  = jj >> 10;
    int r   = jj & 1023;
    int nh  = r >> 8;
    int g   = (r >> 6) & 3;
    int utp = (r >> 5) & 1;
    int lane = r & 31;
    int gid = lane >> 2, t4 = lane & 3;
    float v[4];
    #pragma unroll
    for (int jx = 0; jx < 4; ++jx) {
      int ut = utp * 2 + (jx >> 1);
      int k  = t4 + 4 * (jx & 1);
      int grow = g * 128 + nh * 32 + ut * 8 + gid;
      float val;
      if (!lay) {
        if (kt < 11) { int col = kt * 8 + k; val = (col < INW) ? Wih0[grow * INW + col] : 0.0f; }
        else         { val = Whh0[grow * H + (kt - 11) * 8 + k]; }
      } else {
        if (kt < 16) val = Wih1[grow * H + kt * 8 + k];
        else         val = Whh1[grow * H + (kt - 16) * 8 + k];
      }
      v[jx] = tf32r(val);
    }
    float4 f4 = make_float4(v[0], v[1], v[2], v[3]);
    if (lay) g_F1[jj] = f4; else g_F0[jj] = f4;
    return;
  }
  j -= NB;
  if (j < H * WP) {
    int kk = j / WP, o = j % WP;
    g_Wd[j] = (o < OUTW) ? Wd[o * H + kk] : 0.0f;
    return;
  }
  j -= H * WP;
  if (j < GATES) { g_b0[j] = bih0[j] + bhh0[j]; return; }
  j -= GATES;
  if (j < GATES) { g_b1[j] = bih1[j] + bhh1[j]; return; }
}

// 64 batch rows/CTA, 512 threads (16 warps: mw = 16-row stripe, nh = 32-unit group)
__global__ void __launch_bounds__(NTHR, 1)
lstm_main(const float* __restrict__ x, const float* __restrict__ bd, float* __restrict__ out)
{
  extern __shared__ float sm[];
  float* uS  = sm + OFF_U;     // [64][UP] cols 86..91 zero
  float* h1S = sm + OFF_H1;    // [2][64][HP]
  float* h2S = sm + OFF_H2;
  float* wdS = sm + OFF_WD;    // [128][WP]
  float* b0S = sm + OFF_B0;
  float* b1S = sm + OFF_B1;

  const int tid  = threadIdx.x;
  const int lane = tid & 31, w = tid >> 5;
  const int mw = w & 3, nh = w >> 2;     // mw: 0..3, nh: 0..3
  const int gid = lane >> 2, t4 = lane & 3;
  const int rbase = mw * 16;
  const int row0  = blockIdx.x * BT;
  const int ncol0 = nh * 32;

  for (int i = tid; i < 2 * HBUF; i += NTHR) { h1S[i] = 0.0f; h2S[i] = 0.0f; }
  for (int i = tid; i < BT * UP; i += NTHR) uS[i] = 0.0f;
  for (int i = tid; i < H * WP; i += NTHR) wdS[i] = g_Wd[i];
  for (int i = tid; i < GATES; i += NTHR) { b0S[i] = g_b0[i]; b1S[i] = g_b1[i]; }
  __syncthreads();
  for (int i = tid; i < BT * INW; i += NTHR) {
    int r = i / INW, c = i % INW;
    uS[r * UP + c] = x[(size_t)(row0 + r) * (TSEQ * INW) + c];
  }

  float c1[4][4], c2[4][4];
  #pragma unroll
  for (int ut = 0; ut < 4; ++ut)
    #pragma unroll
    for (int sl = 0; sl < 4; ++sl) { c1[ut][sl] = 0.0f; c2[ut][sl] = 0.0f; }

  const float4* f0 = g_F0 + nh * 256 + lane;
  const float4* f1 = g_F1 + nh * 256 + lane;
  __syncthreads();

  for (int s = 0; s < NSTEP; ++s) {
    const int cur = s & 1, nxt = cur ^ 1;
    float acc[4][4][4];

    // layer 0: gates = u@Wih0^T + h1@Whh0^T + b0
    bias_init(acc, b0S, ncol0, t4);
    gemm_part<11>(acc, uS + rbase * UP, UP, f0, gid, t4);
    gemm_part<16>(acc, h1S + cur * HBUF + rbase * HP, HP, f0 + 11 * 1024, gid, t4);
    cell_store(acc, c1, h1S + nxt * HBUF, rbase, gid, t4, ncol0);
    __syncthreads();   // h1[nxt] visible; uS reads done

    if (s + 1 <= TSEQ) {
      int t = (s + 1 < TSEQ) ? (s + 1) : (TSEQ - 1);
      for (int i = tid; i < BT * INW; i += NTHR) {
        int r = i / INW, c = i % INW;
        uS[r * UP + c] = x[(size_t)(row0 + r) * (TSEQ * INW) + t * INW + c];
      }
    }

    // layer 1: gates = h1@Wih1^T + h2@Whh1^T + b1
    bias_init(acc, b1S, ncol0, t4);
    gemm_part<16>(acc, h1S + nxt * HBUF + rbase * HP, HP, f1, gid, t4);
    gemm_part<16>(acc, h2S + cur * HBUF + rbase * HP, HP, f1 + 16 * 1024, gid, t4);
    cell_store(acc, c2, h2S + nxt * HBUF, rbase, gid, t4, ncol0);
    __syncthreads();   // h2[nxt] + staged u visible

    // dense head (steps 50..64): pose = h2 @ Wd^T + bd
    if (s >= TSEQ) {
      const int so = s - TSEQ;
      const int r = tid >> 3;         // 512 thr -> 64 rows x 8 o-lanes
      const int ob = tid & 7;
      const float* h2r = h2S + nxt * HBUF + r * HP;
      float pose[9];
      #pragma unroll
      for (int jj = 0; jj < 9; ++jj) {
        int o = ob + 8 * jj;
        pose[jj] = (o < OUTW) ? __ldg(bd + o) : 0.0f;
      }
      #pragma unroll 4
      for (int kk = 0; kk < H; ++kk) {
        float hv = h2r[kk];
        const float* wr = wdS + kk * WP + ob;
        #pragma unroll
        for (int jj = 0; jj < 9; ++jj) pose[jj] += hv * wr[8 * jj];
      }
      float* uR = uS + r * UP;
      #pragma unroll
      for (int jj = 0; jj < 9; ++jj) {
        int o = ob + 8 * jj;
        if (o < OUTW) {
          out[(size_t)(row0 + r) * (RSTEPS * OUTW) + so * OUTW + o] = pose[jj];
          uR[o] = pose[jj];   // pose -> next u[0..65]; cond cols 66..85 persist
        }
      }
      __syncthreads(); // pose visible for next layer0
    }
  }
}

extern "C" void kernel_launch(void* const* d_in, const int* in_sizes, int n_in,
                              void* d_out, int out_size)
{
  const float* x    = (const float*)d_in[0];
  const float* Wih0 = (const float*)d_in[1];
  const float* Whh0 = (const float*)d_in[2];
  const float* bih0 = (const float*)d_in[3];
  const float* bhh0 = (const float*)d_in[4];
  const float* Wih1 = (const float*)d_in[5];
  const float* Whh1 = (const float*)d_in[6];
  const float* bih1 = (const float*)d_in[7];
  const float* bhh1 = (const float*)d_in[8];
  const float* Wd   = (const float*)d_in[9];
  const float* bd   = (const float*)d_in[10];
  float* out = (float*)d_out;

  const int B = in_sizes[0] / (TSEQ * INW);   // 8192

  cudaFuncSetAttribute(lstm_main, cudaFuncAttributeMaxDynamicSharedMemorySize, SMEM_BYTES);

  const int prep_n = (KT0 + KT1) * 1024 + H * WP + 2 * GATES;
  prep_kernel<<<(prep_n + 255) / 256, 256>>>(Wih0, Whh0, bih0, bhh0,
                                             Wih1, Whh1, bih1, bhh1, Wd);
  lstm_main<<<B / BT, NTHR, SMEM_BYTES>>>(x, bd, out);
}

// round 11
// speedup vs baseline: 3.2382x; 1.3401x over previous
#include <cuda_runtime.h>
#include <cstdint>

#define H      128
#define INW    86
#define OUTW   66
#define GATES  512
#define TSEQ   50
#define NSTEP  65
#define RSTEPS 15
#define BT     64
#define NTHR   512

#define KT0    27    // layer0 k-tiles: 11 (u, K=88 padded) + 16 (h1)
#define KT1    32    // layer1: 16 (h1) + 16 (h2)
#define UP     92    // u smem pitch
#define HP     132   // h smem pitch
#define WP     72    // WdT smem pitch (cols 66..71 zero)

#define OFF_U   0
#define OFF_H1  (BT * UP)
#define HBUF    (BT * HP)
#define OFF_H2  (OFF_H1 + 2 * HBUF)
#define OFF_WD  (OFF_H2 + 2 * HBUF)
#define OFF_B0  (OFF_WD + H * WP)
#define OFF_B1  (OFF_B0 + GATES)
#define SMEM_FLOATS (OFF_B1 + GATES)
#define SMEM_BYTES  (SMEM_FLOATS * 4)   // ~200 KB

// packed tf32 weight fragments:
// idx = kt*1024 + nh*256 + g*64 + utp*32 + lane
// float4 = { B(k=t4,ut=2utp), B(t4+4,2utp), B(t4,2utp+1), B(t4+4,2utp+1) }, n=gid
// B(k,n) = W[g*128 + nh*32 + ut*8 + n][kbase + k]
__device__ float4 g_F0[KT0 * 1024];
__device__ float4 g_F1[KT1 * 1024];
__device__ float  g_Wd[H * WP];
__device__ float  g_b0[GATES];
__device__ float  g_b1[GATES];

__device__ __forceinline__ uint32_t cvtf(float x){
  uint32_t r; asm("cvt.rna.tf32.f32 %0, %1;" : "=r"(r) : "f"(x)); return r;
}
__device__ __forceinline__ float tf32r(float x){ return __uint_as_float(cvtf(x)); }
__device__ __forceinline__ void mma8(float* d, uint32_t a0, uint32_t a1, uint32_t a2, uint32_t a3,
                                     float bx, float by){
  asm volatile("mma.sync.aligned.m16n8k8.row.col.f32.tf32.tf32.f32 "
               "{%0,%1,%2,%3},{%4,%5,%6,%7},{%8,%9},{%0,%1,%2,%3};"
               : "+f"(d[0]), "+f"(d[1]), "+f"(d[2]), "+f"(d[3])
               : "r"(a0), "r"(a1), "r"(a2), "r"(a3),
                 "r"(__float_as_uint(bx)), "r"(__float_as_uint(by)));
}
__device__ __forceinline__ float sigf(float x){ return __fdividef(1.0f, 1.0f + __expf(-x)); }
__device__ __forceinline__ float tanhfast(float x){ return __fdividef(2.0f, 1.0f + __expf(-2.0f * x)) - 1.0f; }

// plain tf32 GEMM: acc += tf32(A) * B   (B tf32 from prep)
template<int NKT>
__device__ __forceinline__ void gemm_part(float acc[4][4][4], const float* __restrict__ Abase,
                                          int pitch, const float4* __restrict__ bp0,
                                          int gid, int t4)
{
  #pragma unroll 2
  for (int kt = 0; kt < NKT; ++kt) {
    const float* ar = Abase + kt * 8 + t4;
    uint32_t h0 = cvtf(ar[gid * pitch]);
    uint32_t h1 = cvtf(ar[(gid + 8) * pitch]);
    uint32_t h2 = cvtf(ar[gid * pitch + 4]);
    uint32_t h3 = cvtf(ar[(gid + 8) * pitch + 4]);
    const float4* bb = bp0 + kt * 1024;
    #pragma unroll
    for (int g = 0; g < 4; ++g)
      #pragma unroll
      for (int utp = 0; utp < 2; ++utp) {
        float4 bv = __ldg(bb + (g * 2 + utp) * 32);
        mma8(acc[g][2 * utp],     h0, h1, h2, h3, bv.x, bv.y);
        mma8(acc[g][2 * utp + 1], h0, h1, h2, h3, bv.z, bv.w);
      }
  }
}

__device__ __forceinline__ void bias_init(float acc[4][4][4], const float* __restrict__ bS,
                                          int ncol0, int t4)
{
  #pragma unroll
  for (int g = 0; g < 4; ++g)
    #pragma unroll
    for (int ut = 0; ut < 4; ++ut) {
      float2 bb = *reinterpret_cast<const float2*>(&bS[g * 128 + ncol0 + ut * 8 + 2 * t4]);
      acc[g][ut][0] = bb.x; acc[g][ut][1] = bb.y;
      acc[g][ut][2] = bb.x; acc[g][ut][3] = bb.y;
    }
}

// slots: 0,1 -> row rbase+gid cols c,c+1 ; 2,3 -> row rbase+gid+8
__device__ __forceinline__ void cell_store(float acc[4][4][4], float cst[4][4],
                                           float* __restrict__ hb,
                                           int rbase, int gid, int t4, int ncol0)
{
  #pragma unroll
  for (int ut = 0; ut < 4; ++ut) {
    float hv[4];
    #pragma unroll
    for (int sl = 0; sl < 4; ++sl) {
      float cc = sigf(acc[1][ut][sl]) * cst[ut][sl]
               + sigf(acc[0][ut][sl]) * tanhfast(acc[2][ut][sl]);
      cst[ut][sl] = cc;
      hv[sl] = sigf(acc[3][ut][sl]) * tanhfast(cc);
    }
    int c = ncol0 + ut * 8 + 2 * t4;
    *reinterpret_cast<float2*>(&hb[(rbase + gid) * HP + c])     = make_float2(hv[0], hv[1]);
    *reinterpret_cast<float2*>(&hb[(rbase + gid + 8) * HP + c]) = make_float2(hv[2], hv[3]);
  }
}

__global__ void prep_kernel(const float* __restrict__ Wih0, const float* __restrict__ Whh0,
                            const float* __restrict__ bih0, const float* __restrict__ bhh0,
                            const float* __restrict__ Wih1, const float* __restrict__ Whh1,
                            const float* __restrict__ bih1, const float* __restrict__ bhh1,
                            const float* __restrict__ Wd)
{
  int j = blockIdx.x * blockDim.x + threadIdx.x;
  const int NB = (KT0 + KT1) * 1024;
  if (j < NB) {
    int lay = (j >= KT0 * 1024);
    int jj  = lay ? j - KT0 * 1024 : j;
    int kt  = jj >> 10;
    int r   = jj & 1023;
    int nh  = r >> 8;
    int g   = (r >> 6) & 3;
    int utp = (r >> 5) & 1;
    int lane = r & 31;
    int gid = lane >> 2, t4 = lane & 3;
    float v[4];
    #pragma unroll
    for (int jx = 0; jx < 4; ++jx) {
      int ut = utp * 2 + (jx >> 1);
      int k  = t4 + 4 * (jx & 1);
      int grow = g * 128 + nh * 32 + ut * 8 + gid;
      float val;
      if (!lay) {
        if (kt < 11) { int col = kt * 8 + k; val = (col < INW) ? Wih0[grow * INW + col] : 0.0f; }
        else         { val = Whh0[grow * H + (kt - 11) * 8 + k]; }
      } else {
        if (kt < 16) val = Wih1[grow * H + kt * 8 + k];
        else         val = Whh1[grow * H + (kt - 16) * 8 + k];
      }
      v[jx] = tf32r(val);
    }
    float4 f4 = make_float4(v[0], v[1], v[2], v[3]);
    if (lay) g_F1[jj] = f4; else g_F0[jj] = f4;
    return;
  }
  j -= NB;
  if (j < H * WP) {
    int kk = j / WP, o = j % WP;
    g_Wd[j] = (o < OUTW) ? Wd[o * H + kk] : 0.0f;
    return;
  }
  j -= H * WP;
  if (j < GATES) { g_b0[j] = bih0[j] + bhh0[j]; return; }
  j -= GATES;
  if (j < GATES) { g_b1[j] = bih1[j] + bhh1[j]; return; }
}

// 64 batch rows/CTA, 512 threads (16 warps: mw = 16-row stripe, nh = 32-unit group)
__global__ void __launch_bounds__(NTHR, 1)
lstm_main(const float* __restrict__ x, const float* __restrict__ bd, float* __restrict__ out)
{
  extern __shared__ float sm[];
  float* uS  = sm + OFF_U;     // [64][UP] cols 86..91 zero
  float* h1S = sm + OFF_H1;    // [2][64][HP]
  float* h2S = sm + OFF_H2;
  float* wdS = sm + OFF_WD;    // [128][WP]
  float* b0S = sm + OFF_B0;
  float* b1S = sm + OFF_B1;

  const int tid  = threadIdx.x;
  const int lane = tid & 31, w = tid >> 5;
  const int mw = w & 3, nh = w >> 2;     // mw: 0..3, nh: 0..3
  const int gid = lane >> 2, t4 = lane & 3;
  const int rbase = mw * 16;
  const int row0  = blockIdx.x * BT;
  const int ncol0 = nh * 32;

  for (int i = tid; i < 2 * HBUF; i += NTHR) { h1S[i] = 0.0f; h2S[i] = 0.0f; }
  for (int i = tid; i < BT * UP; i += NTHR) uS[i] = 0.0f;
  for (int i = tid; i < H * WP; i += NTHR) wdS[i] = g_Wd[i];
  for (int i = tid; i < GATES; i += NTHR) { b0S[i] = g_b0[i]; b1S[i] = g_b1[i]; }
  __syncthreads();
  for (int i = tid; i < BT * INW; i += NTHR) {
    int r = i / INW, c = i % INW;
    uS[r * UP + c] = x[(size_t)(row0 + r) * (TSEQ * INW) + c];
  }

  float c1[4][4], c2[4][4];
  #pragma unroll
  for (int ut = 0; ut < 4; ++ut)
    #pragma unroll
    for (int sl = 0; sl < 4; ++sl) { c1[ut][sl] = 0.0f; c2[ut][sl] = 0.0f; }

  const float4* f0 = g_F0 + nh * 256 + lane;
  const float4* f1 = g_F1 + nh * 256 + lane;
  __syncthreads();

  for (int s = 0; s < NSTEP; ++s) {
    const int cur = s & 1, nxt = cur ^ 1;
    float acc[4][4][4];

    // layer 0: gates = u@Wih0^T + h1@Whh0^T + b0
    bias_init(acc, b0S, ncol0, t4);
    gemm_part<11>(acc, uS + rbase * UP, UP, f0, gid, t4);
    gemm_part<16>(acc, h1S + cur * HBUF + rbase * HP, HP, f0 + 11 * 1024, gid, t4);
    cell_store(acc, c1, h1S + nxt * HBUF, rbase, gid, t4, ncol0);
    __syncthreads();   // h1[nxt] visible; uS reads done

    if (s + 1 <= TSEQ) {
      int t = (s + 1 < TSEQ) ? (s + 1) : (TSEQ - 1);
      for (int i = tid; i < BT * INW; i += NTHR) {
        int r = i / INW, c = i % INW;
        uS[r * UP + c] = x[(size_t)(row0 + r) * (TSEQ * INW) + t * INW + c];
      }
    }

    // layer 1: gates = h1@Wih1^T + h2@Whh1^T + b1
    bias_init(acc, b1S, ncol0, t4);
    gemm_part<16>(acc, h1S + nxt * HBUF + rbase * HP, HP, f1, gid, t4);
    gemm_part<16>(acc, h2S + cur * HBUF + rbase * HP, HP, f1 + 16 * 1024, gid, t4);
    cell_store(acc, c2, h2S + nxt * HBUF, rbase, gid, t4, ncol0);
    __syncthreads();   // h2[nxt] + staged u visible

    // dense head (steps 50..64): pose = h2 @ Wd^T + bd
    if (s >= TSEQ) {
      const int so = s - TSEQ;
      const int r = tid >> 3;         // 512 thr -> 64 rows x 8 o-lanes
      const int ob = tid & 7;
      const float* h2r = h2S + nxt * HBUF + r * HP;
      float pose[9];
      #pragma unroll
      for (int jj = 0; jj < 9; ++jj) {
        int o = ob + 8 * jj;
        pose[jj] = (o < OUTW) ? __ldg(bd + o) : 0.0f;
      }
      #pragma unroll 4
      for (int kk = 0; kk < H; ++kk) {
        float hv = h2r[kk];
        const float* wr = wdS + kk * WP + ob;
        #pragma unroll
        for (int jj = 0; jj < 9; ++jj) pose[jj] += hv * wr[8 * jj];
      }
      float* uR = uS + r * UP;
      #pragma unroll
      for (int jj = 0; jj < 9; ++jj) {
        int o = ob + 8 * jj;
        if (o < OUTW) {
          out[(size_t)(row0 + r) * (RSTEPS * OUTW) + so * OUTW + o] = pose[jj];
          uR[o] = pose[jj];   // pose -> next u[0..65]; cond cols 66..85 persist
        }
      }
      __syncthreads(); // pose visible for next layer0
    }
  }
}

extern "C" void kernel_launch(void* const* d_in, const int* in_sizes, int n_in,
                              void* d_out, int out_size)
{
  const float* x    = (const float*)d_in[0];
  const float* Wih0 = (const float*)d_in[1];
  const float* Whh0 = (const float*)d_in[2];
  const float* bih0 = (const float*)d_in[3];
  const float* bhh0 = (const float*)d_in[4];
  const float* Wih1 = (const float*)d_in[5];
  const float* Whh1 = (const float*)d_in[6];
  const float* bih1 = (const float*)d_in[7];
  const float* bhh1 = (const float*)d_in[8];
  const float* Wd   = (const float*)d_in[9];
  const float* bd   = (const float*)d_in[10];
  float* out = (float*)d_out;

  const int B = in_sizes[0] / (TSEQ * INW);   // 8192

  cudaFuncSetAttribute(lstm_main, cudaFuncAttributeMaxDynamicSharedMemorySize, SMEM_BYTES);

  const int prep_n = (KT0 + KT1) * 1024 + H * WP + 2 * GATES;
  prep_kernel<<<(prep_n + 255) / 256, 256>>>(Wih0, Whh0, bih0, bhh0,
                                             Wih1, Whh1, bih1, bhh1, Wd);
  lstm_main<<<B / BT, NTHR, SMEM_BYTES>>>(x, bd, out);
}

// round 12
// speedup vs baseline: 3.2917x; 1.0165x over previous
#include <cuda_runtime.h>
#include <cstdint>

#define H      128
#define INW    86
#define OUTW   66
#define GATES  512
#define TSEQ   50
#define NSTEP  65
#define RSTEPS 15
#define BT     64
#define NTHR   256

#define KT0    27    // layer0 k-tiles: 11 (u, K=88 padded) + 16 (h1)
#define KT1    32    // layer1: 16 (h1) + 16 (h2)
#define UP     92    // u smem pitch
#define HP     132   // h smem pitch
#define WP     72    // WdT smem pitch (cols 66..71 zero)

#define OFF_U   0
#define OFF_H1  (BT * UP)
#define HBUF    (BT * HP)
#define OFF_H2  (OFF_H1 + 2 * HBUF)
#define OFF_WD  (OFF_H2 + 2 * HBUF)
#define OFF_B0  (OFF_WD + H * WP)
#define OFF_B1  (OFF_B0 + GATES)
#define SMEM_FLOATS (OFF_B1 + GATES)
#define SMEM_BYTES  (SMEM_FLOATS * 4)   // ~200 KB

// packed tf32 weight fragments:
// idx = kt*1024 + nh*256 + g*64 + utp*32 + lane
// float4 = { B(k=t4,ut=2utp), B(t4+4,2utp), B(t4,2utp+1), B(t4+4,2utp+1) }, n=gid
// B(k,n) = W[g*128 + nh*32 + ut*8 + n][kbase + k]
__device__ float4 g_F0[KT0 * 1024];
__device__ float4 g_F1[KT1 * 1024];
__device__ float  g_Wd[H * WP];
__device__ float  g_b0[GATES];
__device__ float  g_b1[GATES];

__device__ __forceinline__ uint32_t cvtf(float x){
  uint32_t r; asm("cvt.rna.tf32.f32 %0, %1;" : "=r"(r) : "f"(x)); return r;
}
__device__ __forceinline__ float tf32r(float x){ return __uint_as_float(cvtf(x)); }
__device__ __forceinline__ void mma8(float* d, uint32_t a0, uint32_t a1, uint32_t a2, uint32_t a3,
                                     float bx, float by){
  asm volatile("mma.sync.aligned.m16n8k8.row.col.f32.tf32.tf32.f32 "
               "{%0,%1,%2,%3},{%4,%5,%6,%7},{%8,%9},{%0,%1,%2,%3};"
               : "+f"(d[0]), "+f"(d[1]), "+f"(d[2]), "+f"(d[3])
               : "r"(a0), "r"(a1), "r"(a2), "r"(a3),
                 "r"(__float_as_uint(bx)), "r"(__float_as_uint(by)));
}
__device__ __forceinline__ float sigf(float x){ return __fdividef(1.0f, 1.0f + __expf(-x)); }
__device__ __forceinline__ float tanhfast(float x){ return __fdividef(2.0f, 1.0f + __expf(-2.0f * x)) - 1.0f; }

// plain tf32 GEMM over NKT k-tiles; warp covers m32 (2 m16 stripes) x n32.
// One 8xLDG.128 B-fetch now feeds 32 mmas (B read 2x per CTA instead of 4x).
template<int NKT>
__device__ __forceinline__ void gemm_part(float acc[2][4][4][4], const float* __restrict__ Abase,
                                          int pitch, const float4* __restrict__ bp0,
                                          int gid, int t4)
{
  #pragma unroll 2
  for (int kt = 0; kt < NKT; ++kt) {
    const float* ar = Abase + kt * 8 + t4;
    uint32_t a[2][4];
    #pragma unroll
    for (int st = 0; st < 2; ++st) {
      const float* as = ar + st * 16 * pitch;
      a[st][0] = cvtf(as[gid * pitch]);
      a[st][1] = cvtf(as[(gid + 8) * pitch]);
      a[st][2] = cvtf(as[gid * pitch + 4]);
      a[st][3] = cvtf(as[(gid + 8) * pitch + 4]);
    }
    const float4* bb = bp0 + kt * 1024;
    #pragma unroll
    for (int g = 0; g < 4; ++g)
      #pragma unroll
      for (int utp = 0; utp < 2; ++utp) {
        float4 bv = __ldg(bb + (g * 2 + utp) * 32);
        #pragma unroll
        for (int st = 0; st < 2; ++st) {
          mma8(acc[st][g][2 * utp],     a[st][0], a[st][1], a[st][2], a[st][3], bv.x, bv.y);
          mma8(acc[st][g][2 * utp + 1], a[st][0], a[st][1], a[st][2], a[st][3], bv.z, bv.w);
        }
      }
  }
}

__device__ __forceinline__ void bias_init(float acc[2][4][4][4], const float* __restrict__ bS,
                                          int ncol0, int t4)
{
  #pragma unroll
  for (int g = 0; g < 4; ++g)
    #pragma unroll
    for (int ut = 0; ut < 4; ++ut) {
      float2 bb = *reinterpret_cast<const float2*>(&bS[g * 128 + ncol0 + ut * 8 + 2 * t4]);
      #pragma unroll
      for (int st = 0; st < 2; ++st) {
        acc[st][g][ut][0] = bb.x; acc[st][g][ut][1] = bb.y;
        acc[st][g][ut][2] = bb.x; acc[st][g][ut][3] = bb.y;
      }
    }
}

// slots: 0,1 -> row rbase+st*16+gid cols c,c+1 ; 2,3 -> row +8
__device__ __forceinline__ void cell_store(float acc[2][4][4][4], float cst[2][4][4],
                                           float* __restrict__ hb,
                                           int rbase, int gid, int t4, int ncol0)
{
  #pragma unroll
  for (int st = 0; st < 2; ++st) {
    const int rb = rbase + st * 16;
    #pragma unroll
    for (int ut = 0; ut < 4; ++ut) {
      float hv[4];
      #pragma unroll
      for (int sl = 0; sl < 4; ++sl) {
        float cc = sigf(acc[st][1][ut][sl]) * cst[st][ut][sl]
                 + sigf(acc[st][0][ut][sl]) * tanhfast(acc[st][2][ut][sl]);
        cst[st][ut][sl] = cc;
        hv[sl] = sigf(acc[st][3][ut][sl]) * tanhfast(cc);
      }
      int c = ncol0 + ut * 8 + 2 * t4;
      *reinterpret_cast<float2*>(&hb[(rb + gid) * HP + c])     = make_float2(hv[0], hv[1]);
      *reinterpret_cast<float2*>(&hb[(rb + gid + 8) * HP + c]) = make_float2(hv[2], hv[3]);
    }
  }
}

__global__ void prep_kernel(const float* __restrict__ Wih0, const float* __restrict__ Whh0,
                            const float* __restrict__ bih0, const float* __restrict__ bhh0,
                            const float* __restrict__ Wih1, const float* __restrict__ Whh1,
                            const float* __restrict__ bih1, const float* __restrict__ bhh1,
                            const float* __restrict__ Wd)
{
  int j = blockIdx.x * blockDim.x + threadIdx.x;
  const int NB = (KT0 + KT1) * 1024;
  if (j < NB) {
    int lay = (j >= KT0 * 1024);
    int jj  = lay ? j - KT0 * 1024 : j;
    int kt  = jj >> 10;
    int r   = jj & 1023;
    int nh  = r >> 8;
    int g   = (r >> 6) & 3;
    int utp = (r >> 5) & 1;
    int lane = r & 31;
    int gid = lane >> 2, t4 = lane & 3;
    float v[4];
    #pragma unroll
    for (int jx = 0; jx < 4; ++jx) {
      int ut = utp * 2 + (jx >> 1);
      int k  = t4 + 4 * (jx & 1);
      int grow = g * 128 + nh * 32 + ut * 8 + gid;
      float val;
      if (!lay) {
        if (kt < 11) { int col = kt * 8 + k; val = (col < INW) ? Wih0[grow * INW + col] : 0.0f; }
        else         { val = Whh0[grow * H + (kt - 11) * 8 + k]; }
      } else {
        if (kt < 16) val = Wih1[grow * H + kt * 8 + k];
        else         val = Whh1[grow * H + (kt - 16) * 8 + k];
      }
      v[jx] = tf32r(val);
    }
    float4 f4 = make_float4(v[0], v[1], v[2], v[3]);
    if (lay) g_F1[jj] = f4; else g_F0[jj] = f4;
    return;
  }
  j -= NB;
  if (j < H * WP) {
    int kk = j / WP, o = j % WP;
    g_Wd[j] = (o < OUTW) ? Wd[o * H + kk] : 0.0f;
    return;
  }
  j -= H * WP;
  if (j < GATES) { g_b0[j] = bih0[j] + bhh0[j]; return; }
  j -= GATES;
  if (j < GATES) { g_b1[j] = bih1[j] + bhh1[j]; return; }
}

// 64 batch rows/CTA, 256 threads = 8 warps: mw (0..1) = m32 half, nh (0..3) = n32 group.
__global__ void __launch_bounds__(NTHR, 1)
lstm_main(const float* __restrict__ x, const float* __restrict__ bd, float* __restrict__ out)
{
  extern __shared__ float sm[];
  float* uS  = sm + OFF_U;     // [64][UP] cols 86..91 zero
  float* h1S = sm + OFF_H1;    // [2][64][HP]
  float* h2S = sm + OFF_H2;
  float* wdS = sm + OFF_WD;    // [128][WP]
  float* b0S = sm + OFF_B0;
  float* b1S = sm + OFF_B1;

  const int tid  = threadIdx.x;
  const int lane = tid & 31, w = tid >> 5;
  const int mw = w & 1, nh = w >> 1;     // mw: 0..1, nh: 0..3
  const int gid = lane >> 2, t4 = lane & 3;
  const int rbase = mw * 32;
  const int row0  = blockIdx.x * BT;
  const int ncol0 = nh * 32;

  for (int i = tid; i < 2 * HBUF; i += NTHR) { h1S[i] = 0.0f; h2S[i] = 0.0f; }
  for (int i = tid; i < BT * UP; i += NTHR) uS[i] = 0.0f;
  for (int i = tid; i < H * WP; i += NTHR) wdS[i] = g_Wd[i];
  for (int i = tid; i < GATES; i += NTHR) { b0S[i] = g_b0[i]; b1S[i] = g_b1[i]; }
  __syncthreads();
  for (int i = tid; i < BT * INW; i += NTHR) {
    int r = i / INW, c = i % INW;
    uS[r * UP + c] = x[(size_t)(row0 + r) * (TSEQ * INW) + c];
  }

  float c1[2][4][4], c2[2][4][4];
  #pragma unroll
  for (int st = 0; st < 2; ++st)
    #pragma unroll
    for (int ut = 0; ut < 4; ++ut)
      #pragma unroll
      for (int sl = 0; sl < 4; ++sl) { c1[st][ut][sl] = 0.0f; c2[st][ut][sl] = 0.0f; }

  const float4* f0 = g_F0 + nh * 256 + lane;
  const float4* f1 = g_F1 + nh * 256 + lane;
  __syncthreads();

  for (int s = 0; s < NSTEP; ++s) {
    const int cur = s & 1, nxt = cur ^ 1;
    float acc[2][4][4][4];

    // layer 0: gates = u@Wih0^T + h1@Whh0^T + b0
    bias_init(acc, b0S, ncol0, t4);
    gemm_part<11>(acc, uS + rbase * UP, UP, f0, gid, t4);
    gemm_part<16>(acc, h1S + cur * HBUF + rbase * HP, HP, f0 + 11 * 1024, gid, t4);
    cell_store(acc, c1, h1S + nxt * HBUF, rbase, gid, t4, ncol0);
    __syncthreads();   // h1[nxt] visible; uS reads done

    if (s + 1 <= TSEQ) {
      int t = (s + 1 < TSEQ) ? (s + 1) : (TSEQ - 1);
      for (int i = tid; i < BT * INW; i += NTHR) {
        int r = i / INW, c = i % INW;
        uS[r * UP + c] = x[(size_t)(row0 + r) * (TSEQ * INW) + t * INW + c];
      }
    }

    // layer 1: gates = h1@Wih1^T + h2@Whh1^T + b1
    bias_init(acc, b1S, ncol0, t4);
    gemm_part<16>(acc, h1S + nxt * HBUF + rbase * HP, HP, f1, gid, t4);
    gemm_part<16>(acc, h2S + cur * HBUF + rbase * HP, HP, f1 + 16 * 1024, gid, t4);
    cell_store(acc, c2, h2S + nxt * HBUF, rbase, gid, t4, ncol0);
    __syncthreads();   // h2[nxt] + staged u visible

    // dense head (steps 50..64): pose = h2 @ Wd^T + bd
    if (s >= TSEQ) {
      const int so = s - TSEQ;
      const int r = tid >> 2;         // 256 thr -> 64 rows x 4 o-lanes
      const int ob = tid & 3;
      const float* h2r = h2S + nxt * HBUF + r * HP;
      float pose[17];
      #pragma unroll
      for (int jj = 0; jj < 17; ++jj) {
        int o = ob + 4 * jj;
        pose[jj] = (o < OUTW) ? __ldg(bd + o) : 0.0f;
      }
      #pragma unroll 4
      for (int kk = 0; kk < H; ++kk) {
        float hv = h2r[kk];
        const float* wr = wdS + kk * WP + ob;
        #pragma unroll
        for (int jj = 0; jj < 17; ++jj) pose[jj] += hv * wr[4 * jj];
      }
      float* uR = uS + r * UP;
      #pragma unroll
      for (int jj = 0; jj < 17; ++jj) {
        int o = ob + 4 * jj;
        if (o < OUTW) {
          out[(size_t)(row0 + r) * (RSTEPS * OUTW) + so * OUTW + o] = pose[jj];
          uR[o] = pose[jj];   // pose -> next u[0..65]; cond cols 66..85 persist
        }
      }
      __syncthreads(); // pose visible for next layer0
    }
  }
}

extern "C" void kernel_launch(void* const* d_in, const int* in_sizes, int n_in,
                              void* d_out, int out_size)
{
  const float* x    = (const float*)d_in[0];
  const float* Wih0 = (const float*)d_in[1];
  const float* Whh0 = (const float*)d_in[2];
  const float* bih0 = (const float*)d_in[3];
  const float* bhh0 = (const float*)d_in[4];
  const float* Wih1 = (const float*)d_in[5];
  const float* Whh1 = (const float*)d_in[6];
  const float* bih1 = (const float*)d_in[7];
  const float* bhh1 = (const float*)d_in[8];
  const float* Wd   = (const float*)d_in[9];
  const float* bd   = (const float*)d_in[10];
  float* out = (float*)d_out;

  const int B = in_sizes[0] / (TSEQ * INW);   // 8192

  cudaFuncSetAttribute(lstm_main, cudaFuncAttributeMaxDynamicSharedMemorySize, SMEM_BYTES);

  const int prep_n = (KT0 + KT1) * 1024 + H * WP + 2 * GATES;
  prep_kernel<<<(prep_n + 255) / 256, 256>>>(Wih0, Whh0, bih0, bhh0,
                                             Wih1, Whh1, bih1, bhh1, Wd);
  lstm_main<<<B / BT, NTHR, SMEM_BYTES>>>(x, bd, out);
}

// round 13
// speedup vs baseline: 3.5513x; 1.0789x over previous
#include <cuda_runtime.h>
#include <cstdint>

#define H      128
#define INW    86
#define OUTW   66
#define GATES  512
#define TSEQ   50
#define NSTEP  65
#define RSTEPS 15
#define BT     64
#define NTHR   256

#define KT0    27    // layer0 k-tiles: 11 (u, K=88 padded) + 16 (h1)
#define KT1    32    // layer1: 16 (h1) + 16 (h2)
#define NSTREAM 59   // k-tiles per step (periodic B stream)
#define UP     92    // u smem pitch
#define HP     132   // h smem pitch
#define WP     68    // WdT smem pitch (cols 66,67 zero)

// smem layout (floats)
#define OFF_U    0
#define OFF_H1   (BT * UP)                       // 5888
#define HBUF     (BT * HP)                       // 8448
#define OFF_H2   (OFF_H1 + HBUF)
#define OFF_WD   (OFF_H2 + HBUF)                 // 22784
#define OFF_B0   (OFF_WD + H * WP)
#define OFF_B1   (OFF_B0 + GATES)
#define OFF_RING (OFF_B1 + GATES)                // 32512
#define RING_FLOATS (8 * 3 * 1024)               // 8 warps x 3 slots x 4KB
#define SMEM_FLOATS (OFF_RING + RING_FLOATS)
#define SMEM_BYTES  (SMEM_FLOATS * 4)            // 228352 B

// packed tf32 weight fragments:
// idx = kt*1024 + nh*256 + g*64 + utp*32 + lane
// float4 = { B(k=t4,ut=2utp), B(t4+4,2utp), B(t4,2utp+1), B(t4+4,2utp+1) }, n=gid
// B(k,n) = W[g*128 + nh*32 + ut*8 + n][kbase + k]
__device__ float4 g_F0[KT0 * 1024];
__device__ float4 g_F1[KT1 * 1024];
__device__ float  g_Wd[H * WP];
__device__ float  g_b0[GATES];
__device__ float  g_b1[GATES];

__device__ __forceinline__ uint32_t cvtf(float x){
  uint32_t r; asm("cvt.rna.tf32.f32 %0, %1;" : "=r"(r) : "f"(x)); return r;
}
__device__ __forceinline__ float tf32r(float x){ return __uint_as_float(cvtf(x)); }
__device__ __forceinline__ void mma8(float* d, uint32_t a0, uint32_t a1, uint32_t a2, uint32_t a3,
                                     float bx, float by){
  asm volatile("mma.sync.aligned.m16n8k8.row.col.f32.tf32.tf32.f32 "
               "{%0,%1,%2,%3},{%4,%5,%6,%7},{%8,%9},{%0,%1,%2,%3};"
               : "+f"(d[0]), "+f"(d[1]), "+f"(d[2]), "+f"(d[3])
               : "r"(a0), "r"(a1), "r"(a2), "r"(a3),
                 "r"(__float_as_uint(bx)), "r"(__float_as_uint(by)));
}
__device__ __forceinline__ float sigf(float x){ return __fdividef(1.0f, 1.0f + __expf(-x)); }
__device__ __forceinline__ float tanhfast(float x){ return __fdividef(2.0f, 1.0f + __expf(-2.0f * x)) - 1.0f; }

__device__ __forceinline__ void cp16(uint32_t dst, const float4* src){
  asm volatile("cp.async.cg.shared.global [%0], [%1], 16;"
               :: "r"(dst), "l"(src) : "memory");
}
__device__ __forceinline__ void cp_commit(){ asm volatile("cp.async.commit_group;" ::: "memory"); }
template<int N>
__device__ __forceinline__ void cp_wait(){ asm volatile("cp.async.wait_group %0;" :: "n"(N) : "memory"); }

// consume one k-tile: A from smem (2 m16 stripes), B from this warp's ring slot.
__device__ __forceinline__ void consume_tile(float acc[2][4][4][4], const float* ar, int pitch,
                                             const float4* bslot, int gid, int t4)
{
  const float* a0p = ar + t4;
  uint32_t a[2][4];
  #pragma unroll
  for (int st = 0; st < 2; ++st) {
    const float* as = a0p + st * 16 * pitch;
    a[st][0] = cvtf(as[gid * pitch]);
    a[st][1] = cvtf(as[(gid + 8) * pitch]);
    a[st][2] = cvtf(as[gid * pitch + 4]);
    a[st][3] = cvtf(as[(gid + 8) * pitch + 4]);
  }
  #pragma unroll
  for (int f = 0; f < 8; ++f) {
    float4 bv = bslot[f * 32];     // LDS.128, conflict-free
    int g = f >> 1, half = f & 1;
    #pragma unroll
    for (int st = 0; st < 2; ++st)
      mma8(acc[st][g][2 * half + 0], a[st][0], a[st][1], a[st][2], a[st][3], bv.x, bv.y),
      mma8(acc[st][g][2 * half + 1], a[st][0], a[st][1], a[st][2], a[st][3], bv.z, bv.w);
  }
}

__device__ __forceinline__ void bias_init(float acc[2][4][4][4], const float* __restrict__ bS,
                                          int ncol0, int t4)
{
  #pragma unroll
  for (int g = 0; g < 4; ++g)
    #pragma unroll
    for (int ut = 0; ut < 4; ++ut) {
      float2 bb = *reinterpret_cast<const float2*>(&bS[g * 128 + ncol0 + ut * 8 + 2 * t4]);
      #pragma unroll
      for (int st = 0; st < 2; ++st) {
        acc[st][g][ut][0] = bb.x; acc[st][g][ut][1] = bb.y;
        acc[st][g][ut][2] = bb.x; acc[st][g][ut][3] = bb.y;
      }
    }
}

// gates -> (c,h); h kept in regs (acc dead afterwards, ptxas reuses)
__device__ __forceinline__ void cell_update(float acc[2][4][4][4], float cst[2][4][4],
                                            float hv[2][4][4])
{
  #pragma unroll
  for (int st = 0; st < 2; ++st)
    #pragma unroll
    for (int ut = 0; ut < 4; ++ut)
      #pragma unroll
      for (int sl = 0; sl < 4; ++sl) {
        float cc = sigf(acc[st][1][ut][sl]) * cst[st][ut][sl]
                 + sigf(acc[st][0][ut][sl]) * tanhfast(acc[st][2][ut][sl]);
        cst[st][ut][sl] = cc;
        hv[st][ut][sl] = sigf(acc[st][3][ut][sl]) * tanhfast(cc);
      }
}

__device__ __forceinline__ void store_h(float hv[2][4][4], float* __restrict__ hb,
                                        int rbase, int gid, int t4, int ncol0)
{
  #pragma unroll
  for (int st = 0; st < 2; ++st) {
    const int rb = rbase + st * 16;
    #pragma unroll
    for (int ut = 0; ut < 4; ++ut) {
      int c = ncol0 + ut * 8 + 2 * t4;
      *reinterpret_cast<float2*>(&hb[(rb + gid) * HP + c]) =
          make_float2(hv[st][ut][0], hv[st][ut][1]);
      *reinterpret_cast<float2*>(&hb[(rb + gid + 8) * HP + c]) =
          make_float2(hv[st][ut][2], hv[st][ut][3]);
    }
  }
}

__global__ void prep_kernel(const float* __restrict__ Wih0, const float* __restrict__ Whh0,
                            const float* __restrict__ bih0, const float* __restrict__ bhh0,
                            const float* __restrict__ Wih1, const float* __restrict__ Whh1,
                            const float* __restrict__ bih1, const float* __restrict__ bhh1,
                            const float* __restrict__ Wd)
{
  int j = blockIdx.x * blockDim.x + threadIdx.x;
  const int NB = (KT0 + KT1) * 1024;
  if (j < NB) {
    int lay = (j >= KT0 * 1024);
    int jj  = lay ? j - KT0 * 1024 : j;
    int kt  = jj >> 10;
    int r   = jj & 1023;
    int nh  = r >> 8;
    int g   = (r >> 6) & 3;
    int utp = (r >> 5) & 1;
    int lane = r & 31;
    int gid = lane >> 2, t4 = lane & 3;
    float v[4];
    #pragma unroll
    for (int jx = 0; jx < 4; ++jx) {
      int ut = utp * 2 + (jx >> 1);
      int k  = t4 + 4 * (jx & 1);
      int grow = g * 128 + nh * 32 + ut * 8 + gid;
      float val;
      if (!lay) {
        if (kt < 11) { int col = kt * 8 + k; val = (col < INW) ? Wih0[grow * INW + col] : 0.0f; }
        else         { val = Whh0[grow * H + (kt - 11) * 8 + k]; }
      } else {
        if (kt < 16) val = Wih1[grow * H + kt * 8 + k];
        else         val = Whh1[grow * H + (kt - 16) * 8 + k];
      }
      v[jx] = tf32r(val);
    }
    float4 f4 = make_float4(v[0], v[1], v[2], v[3]);
    if (lay) g_F1[jj] = f4; else g_F0[jj] = f4;
    return;
  }
  j -= NB;
  if (j < H * WP) {
    int kk = j / WP, o = j % WP;
    g_Wd[j] = (o < OUTW) ? Wd[o * H + kk] : 0.0f;
    return;
  }
  j -= H * WP;
  if (j < GATES) { g_b0[j] = bih0[j] + bhh0[j]; return; }
  j -= GATES;
  if (j < GATES) { g_b1[j] = bih1[j] + bhh1[j]; return; }
}

// 64 batch rows/CTA, 256 threads = 8 warps: mw (0..1) = m32 half, nh (0..3) = n32 group.
// B fragments stream through a per-warp 3-slot cp.async ring (zero-register prefetch,
// 2 k-tiles ahead, rolls across layers and steps).
__global__ void __launch_bounds__(NTHR, 1)
lstm_main(const float* __restrict__ x, const float* __restrict__ bd, float* __restrict__ out)
{
  extern __shared__ float sm[];
  float* uS  = sm + OFF_U;     // [64][UP] cols 86..91 zero
  float* h1S = sm + OFF_H1;    // [64][HP] single-buffered
  float* h2S = sm + OFF_H2;
  float* wdS = sm + OFF_WD;    // [128][WP]
  float* b0S = sm + OFF_B0;
  float* b1S = sm + OFF_B1;

  const int tid  = threadIdx.x;
  const int lane = tid & 31, w = tid >> 5;
  const int mw = w & 1, nh = w >> 1;     // mw: 0..1, nh: 0..3
  const int gid = lane >> 2, t4 = lane & 3;
  const int rbase = mw * 32;
  const int row0  = blockIdx.x * BT;
  const int ncol0 = nh * 32;

  for (int i = tid; i < 2 * HBUF; i += NTHR) h1S[i] = 0.0f;  // h1 + h2 (contiguous)
  for (int i = tid; i < BT * UP; i += NTHR) uS[i] = 0.0f;
  for (int i = tid; i < H * WP; i += NTHR) wdS[i] = g_Wd[i];
  for (int i = tid; i < GATES; i += NTHR) { b0S[i] = g_b0[i]; b1S[i] = g_b1[i]; }
  __syncthreads();
  for (int i = tid; i < BT * INW; i += NTHR) {
    int r = i / INW, c = i % INW;
    uS[r * UP + c] = x[(size_t)(row0 + r) * (TSEQ * INW) + c];
  }

  float c1[2][4][4], c2[2][4][4];
  #pragma unroll
  for (int st = 0; st < 2; ++st)
    #pragma unroll
    for (int ut = 0; ut < 4; ++ut)
      #pragma unroll
      for (int sl = 0; sl < 4; ++sl) { c1[st][ut][sl] = 0.0f; c2[st][ut][sl] = 0.0f; }

  // per-warp B stream pointers (pre-offset by nh & lane)
  const float4* f0 = g_F0 + nh * 256 + lane;
  const float4* f1 = g_F1 + nh * 256 + lane;
  // ring: per-warp 3 slots x 1024 floats; lane's own 16B per fragment
  const uint32_t ring_u32 =
      (uint32_t)__cvta_generic_to_shared(sm + OFF_RING) + w * 12288 + lane * 16;
  const float4* ringW = reinterpret_cast<const float4*>(sm + OFF_RING) + w * 768 + lane;

  int stg_m = 0, stg_slot = 0;   // next stream index / ring slot to stage
  int cons_slot = 0;             // ring slot of current consume

#define STAGE_NEXT() do { \
    const float4* _src = (stg_m < KT0) ? (f0 + stg_m * 1024) : (f1 + (stg_m - KT0) * 1024); \
    uint32_t _dst = ring_u32 + stg_slot * 4096; \
    _Pragma("unroll") \
    for (int _f = 0; _f < 8; ++_f) cp16(_dst + _f * 512, _src + _f * 32); \
    cp_commit(); \
    stg_m = (stg_m + 1 == NSTREAM) ? 0 : stg_m + 1; \
    stg_slot = (stg_slot + 1 == 3) ? 0 : stg_slot + 1; \
  } while (0)

  STAGE_NEXT();   // stream 0 -> slot 0
  STAGE_NEXT();   // stream 1 -> slot 1
  __syncthreads();

  for (int s = 0; s < NSTEP; ++s) {
    float acc[2][4][4][4], hv[2][4][4];

    // ---- layer 0: gates = u@Wih0^T + h1@Whh0^T + b0 ----
    bias_init(acc, b0S, ncol0, t4);
    {
      const float* aU = uS + rbase * UP;
      #pragma unroll 2
      for (int m = 0; m < 11; ++m) {
        STAGE_NEXT(); cp_wait<2>();
        consume_tile(acc, aU + m * 8, UP, ringW + cons_slot * 256, gid, t4);
        cons_slot = (cons_slot + 1 == 3) ? 0 : cons_slot + 1;
      }
      const float* aH = h1S + rbase * HP;
      #pragma unroll 2
      for (int m = 0; m < 16; ++m) {
        STAGE_NEXT(); cp_wait<2>();
        consume_tile(acc, aH + m * 8, HP, ringW + cons_slot * 256, gid, t4);
        cons_slot = (cons_slot + 1 == 3) ? 0 : cons_slot + 1;
      }
    }
    cell_update(acc, c1, hv);
    __syncthreads();                 // all reads of h1 done
    store_h(hv, h1S, rbase, gid, t4, ncol0);
    __syncthreads();                 // new h1 visible

    // stage u(s+1) from x (overlaps layer 1; visible after the h2 barrier)
    if (s + 1 <= TSEQ) {
      int t = (s + 1 < TSEQ) ? (s + 1) : (TSEQ - 1);
      for (int i = tid; i < BT * INW; i += NTHR) {
        int r = i / INW, c = i % INW;
        uS[r * UP + c] = x[(size_t)(row0 + r) * (TSEQ * INW) + t * INW + c];
      }
    }

    // ---- layer 1: gates = h1@Wih1^T + h2@Whh1^T + b1 ----
    bias_init(acc, b1S, ncol0, t4);
    {
      const float* aH1 = h1S + rbase * HP;
      #pragma unroll 2
      for (int m = 0; m < 16; ++m) {
        STAGE_NEXT(); cp_wait<2>();
        consume_tile(acc, aH1 + m * 8, HP, ringW + cons_slot * 256, gid, t4);
        cons_slot = (cons_slot + 1 == 3) ? 0 : cons_slot + 1;
      }
      const float* aH2 = h2S + rbase * HP;
      #pragma unroll 2
      for (int m = 0; m < 16; ++m) {
        STAGE_NEXT(); cp_wait<2>();
        consume_tile(acc, aH2 + m * 8, HP, ringW + cons_slot * 256, gid, t4);
        cons_slot = (cons_slot + 1 == 3) ? 0 : cons_slot + 1;
      }
    }
    cell_update(acc, c2, hv);
    __syncthreads();                 // all reads of h2 done
    store_h(hv, h2S, rbase, gid, t4, ncol0);
    __syncthreads();                 // new h2 + staged u visible

    // ---- dense head (steps 50..64): pose = h2 @ Wd^T + bd ----
    if (s >= TSEQ) {
      const int so = s - TSEQ;
      const int r = tid >> 2;         // 64 rows x 4 o-lanes
      const int ob = tid & 3;
      const float* h2r = h2S + r * HP;
      float pose[17];
      #pragma unroll
      for (int jj = 0; jj < 17; ++jj) {
        int o = ob + 4 * jj;
        pose[jj] = (o < OUTW) ? __ldg(bd + o) : 0.0f;
      }
      #pragma unroll 4
      for (int kk = 0; kk < H; ++kk) {
        float hvv = h2r[kk];
        const float* wr = wdS + kk * WP + ob;
        #pragma unroll
        for (int jj = 0; jj < 17; ++jj) pose[jj] += hvv * wr[4 * jj];
      }
      float* uR = uS + r * UP;
      #pragma unroll
      for (int jj = 0; jj < 17; ++jj) {
        int o = ob + 4 * jj;
        if (o < OUTW) {
          out[(size_t)(row0 + r) * (RSTEPS * OUTW) + so * OUTW + o] = pose[jj];
          uR[o] = pose[jj];   // pose -> next u[0..65]; cond cols 66..85 persist
        }
      }
      __syncthreads();               // pose visible for next layer0
    }
  }
#undef STAGE_NEXT
}

extern "C" void kernel_launch(void* const* d_in, const int* in_sizes, int n_in,
                              void* d_out, int out_size)
{
  const float* x    = (const float*)d_in[0];
  const float* Wih0 = (const float*)d_in[1];
  const float* Whh0 = (const float*)d_in[2];
  const float* bih0 = (const float*)d_in[3];
  const float* bhh0 = (const float*)d_in[4];
  const float* Wih1 = (const float*)d_in[5];
  const float* Whh1 = (const float*)d_in[6];
  const float* bih1 = (const float*)d_in[7];
  const float* bhh1 = (const float*)d_in[8];
  const float* Wd   = (const float*)d_in[9];
  const float* bd   = (const float*)d_in[10];
  float* out = (float*)d_out;

  const int B = in_sizes[0] / (TSEQ * INW);   // 8192

  cudaFuncSetAttribute(lstm_main, cudaFuncAttributeMaxDynamicSharedMemorySize, SMEM_BYTES);

  const int prep_n = (KT0 + KT1) * 1024 + H * WP + 2 * GATES;
  prep_kernel<<<(prep_n + 255) / 256, 256>>>(Wih0, Whh0, bih0, bhh0,
                                             Wih1, Whh1, bih1, bhh1, Wd);
  lstm_main<<<B / BT, NTHR, SMEM_BYTES>>>(x, bd, out);
}

// round 14
// speedup vs baseline: 3.6038x; 1.0148x over previous
#include <cuda_runtime.h>
#include <cstdint>

#define H      128
#define INW    86
#define OUTW   66
#define GATES  512
#define TSEQ   50
#define NSTEP  65
#define RSTEPS 15
#define BT     32
#define NTHR   256

#define KT0    27    // layer0 k-tiles: 11 (u, K=88 padded) + 16 (h1)
#define KT1    32    // layer1: 16 (h1) + 16 (h2)
#define NSTREAM 59   // k-tiles per step (periodic B stream)
#define UP     92    // u smem pitch
#define HP     132   // h smem pitch
#define WP     72    // Wd row pitch (cols 66..71 zero)

// smem layout (floats), per CTA: 98816 B -> 2 CTAs/SM
#define OFF_U    0
#define OFF_H1   (BT * UP)                       // 2944
#define OFF_H2   (OFF_H1 + BT * HP)              // 7168
#define OFF_B0   (OFF_H2 + BT * HP)              // 11392
#define OFF_B1   (OFF_B0 + GATES)
#define OFF_RING (OFF_B1 + GATES)                // 12416
#define RING_FLOATS (8 * 3 * 512)                // 8 warps x 3 slots x 2KB
#define SMEM_FLOATS (OFF_RING + RING_FLOATS)     // 24704
#define SMEM_BYTES  (SMEM_FLOATS * 4)

// packed tf32 weight fragments (unchanged layout):
// idx = kt*1024 + nh*256 + g*64 + utp*32 + lane
// float4 = { B(k=t4,ut=2utp), B(t4+4,2utp), B(t4,2utp+1), B(t4+4,2utp+1) }, n=gid
// B(k,n) = W[g*128 + nh*32 + ut*8 + n][kbase + k]
// Warp w owns n-slice (nh = w>>1, utp = w&1) -> its 4 frags/tile are at g*64 stride.
__device__ float4 g_F0[KT0 * 1024];
__device__ float4 g_F1[KT1 * 1024];
__device__ float  g_Wd[H * WP];
__device__ float  g_b0[GATES];
__device__ float  g_b1[GATES];

__device__ __forceinline__ uint32_t cvtf(float x){
  uint32_t r; asm("cvt.rna.tf32.f32 %0, %1;" : "=r"(r) : "f"(x)); return r;
}
__device__ __forceinline__ float tf32r(float x){ return __uint_as_float(cvtf(x)); }
__device__ __forceinline__ void mma8(float* d, uint32_t a0, uint32_t a1, uint32_t a2, uint32_t a3,
                                     float bx, float by){
  asm volatile("mma.sync.aligned.m16n8k8.row.col.f32.tf32.tf32.f32 "
               "{%0,%1,%2,%3},{%4,%5,%6,%7},{%8,%9},{%0,%1,%2,%3};"
               : "+f"(d[0]), "+f"(d[1]), "+f"(d[2]), "+f"(d[3])
               : "r"(a0), "r"(a1), "r"(a2), "r"(a3),
                 "r"(__float_as_uint(bx)), "r"(__float_as_uint(by)));
}
__device__ __forceinline__ float sigf(float x){ return __fdividef(1.0f, 1.0f + __expf(-x)); }
__device__ __forceinline__ float tanhfast(float x){ return __fdividef(2.0f, 1.0f + __expf(-2.0f * x)) - 1.0f; }

__device__ __forceinline__ void cp16(uint32_t dst, const float4* src){
  asm volatile("cp.async.cg.shared.global [%0], [%1], 16;"
               :: "r"(dst), "l"(src) : "memory");
}
__device__ __forceinline__ void cp_commit(){ asm volatile("cp.async.commit_group;" ::: "memory"); }
template<int N>
__device__ __forceinline__ void cp_wait(){ asm volatile("cp.async.wait_group %0;" :: "n"(N) : "memory"); }

// consume one k-tile: A bits straight from smem (pre-tf32-rounded), B from warp ring slot.
// Warp covers m32 (2 m16 stripes) x n16-per-gate x 4 gates = 16 mmas.
__device__ __forceinline__ void consume_tile(float acc[2][4][2][4], const float* ar, int pitch,
                                             const float4* bslot, int gid, int t4)
{
  uint32_t a[2][4];
  #pragma unroll
  for (int st = 0; st < 2; ++st) {
    const float* as = ar + st * 16 * pitch + t4;
    a[st][0] = __float_as_uint(as[gid * pitch]);
    a[st][1] = __float_as_uint(as[(gid + 8) * pitch]);
    a[st][2] = __float_as_uint(as[gid * pitch + 4]);
    a[st][3] = __float_as_uint(as[(gid + 8) * pitch + 4]);
  }
  #pragma unroll
  for (int g = 0; g < 4; ++g) {
    float4 bv = bslot[g * 32];     // LDS.128, conflict-free
    #pragma unroll
    for (int st = 0; st < 2; ++st) {
      mma8(acc[st][g][0], a[st][0], a[st][1], a[st][2], a[st][3], bv.x, bv.y);
      mma8(acc[st][g][1], a[st][0], a[st][1], a[st][2], a[st][3], bv.z, bv.w);
    }
  }
}

__device__ __forceinline__ void bias_init(float acc[2][4][2][4], const float* __restrict__ bS,
                                          int ncol0, int t4)
{
  #pragma unroll
  for (int g = 0; g < 4; ++g)
    #pragma unroll
    for (int ut = 0; ut < 2; ++ut) {
      float2 bb = *reinterpret_cast<const float2*>(&bS[g * 128 + ncol0 + ut * 8 + 2 * t4]);
      #pragma unroll
      for (int st = 0; st < 2; ++st) {
        acc[st][g][ut][0] = bb.x; acc[st][g][ut][1] = bb.y;
        acc[st][g][ut][2] = bb.x; acc[st][g][ut][3] = bb.y;
      }
    }
}

// gates -> (c,h); h stored tf32-PRE-ROUNDED (mma A-side needs it; dense head tolerates it)
__device__ __forceinline__ void cell_store(float acc[2][4][2][4], float cst[2][2][4],
                                           float* __restrict__ hb,
                                           int gid, int t4, int ncol0)
{
  #pragma unroll
  for (int st = 0; st < 2; ++st)
    #pragma unroll
    for (int ut = 0; ut < 2; ++ut) {
      float hv[4];
      #pragma unroll
      for (int sl = 0; sl < 4; ++sl) {
        float cc = sigf(acc[st][1][ut][sl]) * cst[st][ut][sl]
                 + sigf(acc[st][0][ut][sl]) * tanhfast(acc[st][2][ut][sl]);
        cst[st][ut][sl] = cc;
        hv[sl] = tf32r(sigf(acc[st][3][ut][sl]) * tanhfast(cc));
      }
      int c = ncol0 + ut * 8 + 2 * t4;
      int rb = st * 16;
      *reinterpret_cast<float2*>(&hb[(rb + gid) * HP + c])     = make_float2(hv[0], hv[1]);
      *reinterpret_cast<float2*>(&hb[(rb + gid + 8) * HP + c]) = make_float2(hv[2], hv[3]);
    }
}

__global__ void prep_kernel(const float* __restrict__ Wih0, const float* __restrict__ Whh0,
                            const float* __restrict__ bih0, const float* __restrict__ bhh0,
                            const float* __restrict__ Wih1, const float* __restrict__ Whh1,
                            const float* __restrict__ bih1, const float* __restrict__ bhh1,
                            const float* __restrict__ Wd)
{
  int j = blockIdx.x * blockDim.x + threadIdx.x;
  const int NB = (KT0 + KT1) * 1024;
  if (j < NB) {
    int lay = (j >= KT0 * 1024);
    int jj  = lay ? j - KT0 * 1024 : j;
    int kt  = jj >> 10;
    int r   = jj & 1023;
    int nh  = r >> 8;
    int g   = (r >> 6) & 3;
    int utp = (r >> 5) & 1;
    int lane = r & 31;
    int gid = lane >> 2, t4 = lane & 3;
    float v[4];
    #pragma unroll
    for (int jx = 0; jx < 4; ++jx) {
      int ut = utp * 2 + (jx >> 1);
      int k  = t4 + 4 * (jx & 1);
      int grow = g * 128 + nh * 32 + ut * 8 + gid;
      float val;
      if (!lay) {
        if (kt < 11) { int col = kt * 8 + k; val = (col < INW) ? Wih0[grow * INW + col] : 0.0f; }
        else         { val = Whh0[grow * H + (kt - 11) * 8 + k]; }
      } else {
        if (kt < 16) val = Wih1[grow * H + kt * 8 + k];
        else         val = Whh1[grow * H + (kt - 16) * 8 + k];
      }
      v[jx] = tf32r(val);
    }
    float4 f4 = make_float4(v[0], v[1], v[2], v[3]);
    if (lay) g_F1[jj] = f4; else g_F0[jj] = f4;
    return;
  }
  j -= NB;
  if (j < H * WP) {
    int kk = j / WP, o = j % WP;
    g_Wd[j] = (o < OUTW) ? Wd[o * H + kk] : 0.0f;
    return;
  }
  j -= H * WP;
  if (j < GATES) { g_b0[j] = bih0[j] + bhh0[j]; return; }
  j -= GATES;
  if (j < GATES) { g_b1[j] = bih1[j] + bhh1[j]; return; }
}

// 32 batch rows/CTA, 256 threads = 8 warps (each m32 x one n16-slice of all 4 gates);
// 2 CTAs/SM for latency hiding; zero B duplication; zero-register cp.async B ring.
__global__ void __launch_bounds__(NTHR, 2)
lstm_main(const float* __restrict__ x, const float* __restrict__ bd, float* __restrict__ out)
{
  extern __shared__ float sm[];
  float* uS  = sm + OFF_U;     // [32][UP] cols 86..91 zero (tf32-rounded)
  float* h1S = sm + OFF_H1;    // [32][HP] (tf32-rounded)
  float* h2S = sm + OFF_H2;
  float* b0S = sm + OFF_B0;
  float* b1S = sm + OFF_B1;

  const int tid  = threadIdx.x;
  const int lane = tid & 31, w = tid >> 5;
  const int gid = lane >> 2, t4 = lane & 3;
  const int row0  = blockIdx.x * BT;
  const int ncol0 = w * 16;                 // warp's 16-unit slice within each gate

  for (int i = tid; i < 2 * BT * HP; i += NTHR) h1S[i] = 0.0f;   // h1+h2 contiguous
  for (int i = tid; i < BT * UP; i += NTHR) uS[i] = 0.0f;
  for (int i = tid; i < GATES; i += NTHR) { b0S[i] = g_b0[i]; b1S[i] = g_b1[i]; }
  __syncthreads();
  for (int i = tid; i < BT * INW; i += NTHR) {
    int r = i / INW, c = i % INW;
    uS[r * UP + c] = tf32r(x[(size_t)(row0 + r) * (TSEQ * INW) + c]);
  }

  float c1[2][2][4], c2[2][2][4];
  #pragma unroll
  for (int st = 0; st < 2; ++st)
    #pragma unroll
    for (int ut = 0; ut < 2; ++ut)
      #pragma unroll
      for (int sl = 0; sl < 4; ++sl) { c1[st][ut][sl] = 0.0f; c2[st][ut][sl] = 0.0f; }

  // per-warp B stream pointers: slice (nh = w>>1, utp = w&1), frags at g*64 stride
  const float4* f0 = g_F0 + (w >> 1) * 256 + (w & 1) * 32 + lane;
  const float4* f1 = g_F1 + (w >> 1) * 256 + (w & 1) * 32 + lane;
  // ring: per-warp 3 slots x 512 floats (2KB); lane's own 16B per fragment
  const uint32_t ring_u32 =
      (uint32_t)__cvta_generic_to_shared(sm + OFF_RING) + w * 6144 + lane * 16;
  const float4* ringW = reinterpret_cast<const float4*>(sm + OFF_RING) + w * 384 + lane;

  int stg_m = 0, stg_slot = 0;
  int cons_slot = 0;

#define STAGE_NEXT() do { \
    const float4* _src = (stg_m < KT0) ? (f0 + stg_m * 1024) : (f1 + (stg_m - KT0) * 1024); \
    uint32_t _dst = ring_u32 + stg_slot * 2048; \
    _Pragma("unroll") \
    for (int _g = 0; _g < 4; ++_g) cp16(_dst + _g * 512, _src + _g * 64); \
    cp_commit(); \
    stg_m = (stg_m + 1 == NSTREAM) ? 0 : stg_m + 1; \
    stg_slot = (stg_slot + 1 == 3) ? 0 : stg_slot + 1; \
  } while (0)

  STAGE_NEXT();
  STAGE_NEXT();
  __syncthreads();

  for (int s = 0; s < NSTEP; ++s) {
    float acc[2][4][2][4];

    // ---- layer 0: gates = u@Wih0^T + h1@Whh0^T + b0 ----
    bias_init(acc, b0S, ncol0, t4);
    #pragma unroll 2
    for (int m = 0; m < 11; ++m) {
      STAGE_NEXT(); cp_wait<2>();
      consume_tile(acc, uS + m * 8, UP, ringW + cons_slot * 128, gid, t4);
      cons_slot = (cons_slot + 1 == 3) ? 0 : cons_slot + 1;
    }
    #pragma unroll 2
    for (int m = 0; m < 16; ++m) {
      STAGE_NEXT(); cp_wait<2>();
      consume_tile(acc, h1S + m * 8, HP, ringW + cons_slot * 128, gid, t4);
      cons_slot = (cons_slot + 1 == 3) ? 0 : cons_slot + 1;
    }
    __syncthreads();                 // all reads of old h1 done
    cell_store(acc, c1, h1S, gid, t4, ncol0);
    __syncthreads();                 // new h1 visible

    // stage u(s+1) from x (overlaps layer 1; visible after the h2 barrier)
    if (s + 1 <= TSEQ) {
      int t = (s + 1 < TSEQ) ? (s + 1) : (TSEQ - 1);
      for (int i = tid; i < BT * INW; i += NTHR) {
        int r = i / INW, c = i % INW;
        uS[r * UP + c] = tf32r(x[(size_t)(row0 + r) * (TSEQ * INW) + t * INW + c]);
      }
    }

    // ---- layer 1: gates = h1@Wih1^T + h2@Whh1^T + b1 ----
    bias_init(acc, b1S, ncol0, t4);
    #pragma unroll 2
    for (int m = 0; m < 16; ++m) {
      STAGE_NEXT(); cp_wait<2>();
      consume_tile(acc, h1S + m * 8, HP, ringW + cons_slot * 128, gid, t4);
      cons_slot = (cons_slot + 1 == 3) ? 0 : cons_slot + 1;
    }
    #pragma unroll 2
    for (int m = 0; m < 16; ++m) {
      STAGE_NEXT(); cp_wait<2>();
      consume_tile(acc, h2S + m * 8, HP, ringW + cons_slot * 128, gid, t4);
      cons_slot = (cons_slot + 1 == 3) ? 0 : cons_slot + 1;
    }
    __syncthreads();                 // all reads of old h2 done
    cell_store(acc, c2, h2S, gid, t4, ncol0);
    __syncthreads();                 // new h2 + staged u visible

    // ---- dense head (steps 50..64): pose = h2 @ Wd^T + bd ----
    if (s >= TSEQ) {
      const int so = s - TSEQ;
      const int r = tid >> 3;         // 32 rows x 8 o-lanes
      const int ob = tid & 7;
      const float* h2r = h2S + r * HP;
      float pose[9];
      #pragma unroll
      for (int jj = 0; jj < 9; ++jj) {
        int o = ob + 8 * jj;
        pose[jj] = (o < OUTW) ? __ldg(bd + o) : 0.0f;
      }
      #pragma unroll 4
      for (int kk = 0; kk < H; ++kk) {
        float hvv = h2r[kk];
        const float* wr = g_Wd + kk * WP + ob;
        #pragma unroll
        for (int jj = 0; jj < 9; ++jj) pose[jj] += hvv * __ldg(wr + 8 * jj);
      }
      float* uR = uS + r * UP;
      #pragma unroll
      for (int jj = 0; jj < 9; ++jj) {
        int o = ob + 8 * jj;
        if (o < OUTW) {
          out[(size_t)(row0 + r) * (RSTEPS * OUTW) + so * OUTW + o] = pose[jj];
          uR[o] = tf32r(pose[jj]);   // pose -> next u[0..65]; cond cols 66..85 persist
        }
      }
      __syncthreads();               // pose visible for next layer0
    }
  }
#undef STAGE_NEXT
}

extern "C" void kernel_launch(void* const* d_in, const int* in_sizes, int n_in,
                              void* d_out, int out_size)
{
  const float* x    = (const float*)d_in[0];
  const float* Wih0 = (const float*)d_in[1];
  const float* Whh0 = (const float*)d_in[2];
  const float* bih0 = (const float*)d_in[3];
  const float* bhh0 = (const float*)d_in[4];
  const float* Wih1 = (const float*)d_in[5];
  const float* Whh1 = (const float*)d_in[6];
  const float* bih1 = (const float*)d_in[7];
  const float* bhh1 = (const float*)d_in[8];
  const float* Wd   = (const float*)d_in[9];
  const float* bd   = (const float*)d_in[10];
  float* out = (float*)d_out;

  const int B = in_sizes[0] / (TSEQ * INW);   // 8192

  cudaFuncSetAttribute(lstm_main, cudaFuncAttributeMaxDynamicSharedMemorySize, SMEM_BYTES);

  const int prep_n = (KT0 + KT1) * 1024 + H * WP + 2 * GATES;
  prep_kernel<<<(prep_n + 255) / 256, 256>>>(Wih0, Whh0, bih0, bhh0,
                                             Wih1, Whh1, bih1, bhh1, Wd);
  lstm_main<<<B / BT, NTHR, SMEM_BYTES>>>(x, bd, out);
}